// round 3
// baseline (speedup 1.0000x reference)
#include <cuda_runtime.h>
#include <cuda_bf16.h>
#include <cstdint>

// Problem shapes (fixed by the dataset's setup_inputs)
#define B_DIM 8
#define S_DIM 4096
#define H_DIM 1024
#define G_DIM 1024
#define NNZ   (B_DIM * S_DIM)          // 32768
#define NSEG  (B_DIM * G_DIM)          // 8192
#define H4    (H_DIM / 4)              // 256 float4 per row

// Scratch (no device allocations allowed)
__device__ int   g_counts[NSEG];
__device__ int   g_offsets[NSEG + 1];
__device__ int   g_cursor[NSEG];
__device__ int   g_rows[NNZ];
__device__ float g_vals[NNZ];
__device__ int   g_is64;

// ---------------------------------------------------------------------------
// 1) Fused: detect indices dtype (block 0) + zero per-segment counts (all
//    blocks). Little-endian int64 with small non-negative values => every odd
//    int32 slot in the first 3*NNZ int32 window is a zero high-word. Under
//    int32 those slots hold real b/g/s index data (plenty nonzero).
// ---------------------------------------------------------------------------
__global__ void init_kernel(const int* __restrict__ p) {
    int i = blockIdx.x * blockDim.x + threadIdx.x;
    if (i < NSEG) g_counts[i] = 0;

    if (blockIdx.x == 0) {
        __shared__ int s_or[256];
        int tid = threadIdx.x;
        int acc = 0;
        for (int k = 1 + 2 * tid; k < 3 * NNZ; k += 2 * 256)
            acc |= p[k];
        s_or[tid] = acc;
        __syncthreads();
        for (int off = 128; off > 0; off >>= 1) {
            if (tid < off) s_or[tid] |= s_or[tid + off];
            __syncthreads();
        }
        if (tid == 0) g_is64 = (s_or[0] == 0) ? 1 : 0;
    }
}

__device__ __forceinline__ void load_bgs(const void* idx, int i, int is64,
                                         int& b, int& g, int& s) {
    if (is64) {
        const long long* q = (const long long*)idx;
        b = (int)q[i];
        g = (int)q[NNZ + i];
        s = (int)q[2 * NNZ + i];
    } else {
        const int* q = (const int*)idx;
        b = q[i];
        g = q[NNZ + i];
        s = q[2 * NNZ + i];
    }
}

// ---------------------------------------------------------------------------
// 2) Count entries per segment
// ---------------------------------------------------------------------------
__global__ void count_kernel(const void* __restrict__ idx) {
    int i = blockIdx.x * blockDim.x + threadIdx.x;
    if (i >= NNZ) return;
    int is64 = g_is64;
    int b, g, s;
    load_bgs(idx, i, is64, b, g, s);
    atomicAdd(&g_counts[b * G_DIM + g], 1);
}

// ---------------------------------------------------------------------------
// 3) Exclusive scan over NSEG counts — single block, 1024 threads.
//    Thread t owns 8 contiguous counts: serial local sum, warp shuffle scan
//    (5 steps), one warp scans the 32 warp totals. 2 barriers total
//    (vs ~160 for Hillis-Steele-over-chunks).
// ---------------------------------------------------------------------------
__global__ void __launch_bounds__(1024) scan_kernel() {
    __shared__ int s_warp[32];
    int tid  = threadIdx.x;
    int lane = tid & 31;
    int wrp  = tid >> 5;

    int v[8];
    int tot = 0;
    int base = tid * 8;
#pragma unroll
    for (int k = 0; k < 8; ++k) { v[k] = g_counts[base + k]; tot += v[k]; }

    // inclusive warp scan of per-thread totals
    int inc = tot;
#pragma unroll
    for (int off = 1; off < 32; off <<= 1) {
        int t = __shfl_up_sync(0xFFFFFFFFu, inc, off);
        if (lane >= off) inc += t;
    }
    if (lane == 31) s_warp[wrp] = inc;
    __syncthreads();

    if (wrp == 0) {
        int w = s_warp[lane];
        int wi = w;
#pragma unroll
        for (int off = 1; off < 32; off <<= 1) {
            int t = __shfl_up_sync(0xFFFFFFFFu, wi, off);
            if (lane >= off) wi += t;
        }
        s_warp[lane] = wi - w;  // exclusive warp prefix
        if (lane == 31 && tid == 31) g_offsets[NSEG] = wi;  // grand total
    }
    __syncthreads();

    int excl = s_warp[wrp] + (inc - tot);  // exclusive prefix for this thread
#pragma unroll
    for (int k = 0; k < 8; ++k) {
        g_offsets[base + k] = excl;
        g_cursor[base + k]  = excl;
        excl += v[k];
    }
}

// ---------------------------------------------------------------------------
// 4) Scatter (row index into feats, value) into bucketed entry lists
// ---------------------------------------------------------------------------
__global__ void scatter_kernel(const void* __restrict__ idx,
                               const float* __restrict__ values) {
    int i = blockIdx.x * blockDim.x + threadIdx.x;
    if (i >= NNZ) return;
    int is64 = g_is64;
    int b, g, s;
    load_bgs(idx, i, is64, b, g, s);
    int seg = b * G_DIM + g;
    int pos = atomicAdd(&g_cursor[seg], 1);
    g_rows[pos] = b * S_DIM + s;
    g_vals[pos] = values[i];
}

// ---------------------------------------------------------------------------
// 5) Dense gather: block = segment, thread = one float4 column chunk.
//    Entry lists are staged to shared memory per 64-entry chunk so the feats
//    loads inside the loop depend only on a 29-cycle LDS, not a serial
//    global-load chain -> compiler can keep multiple 16B loads in flight.
//    feats touched exactly once -> streaming loads (__ldcs); output streamed
//    (__stcs). Double accumulation keeps the rounded float result independent
//    of the nondeterministic scatter order; FP64 time hides under HBM.
// ---------------------------------------------------------------------------
__global__ void __launch_bounds__(256) gather_kernel(
    const float4* __restrict__ feats4, float4* __restrict__ out4) {
    __shared__ int   s_rows[64];
    __shared__ float s_vals[64];

    int seg = blockIdx.x;
    int c   = threadIdx.x;          // 0..255 float4 chunks
    int start = __ldg(&g_offsets[seg]);
    int end   = __ldg(&g_offsets[seg + 1]);

    double a0 = 0.0, a1 = 0.0, a2 = 0.0, a3 = 0.0;
    for (int base = start; base < end; base += 64) {
        int n = min(64, end - base);
        if (c < n) {
            s_rows[c] = g_rows[base + c];
            s_vals[c] = g_vals[base + c];
        }
        __syncthreads();
        for (int j = 0; j < n; ++j) {
            int   row = s_rows[j];
            float v   = s_vals[j];
            float4 f  = __ldcs(&feats4[((size_t)row << 8) + c]);
            a0 += (double)v * (double)f.x;
            a1 += (double)v * (double)f.y;
            a2 += (double)v * (double)f.z;
            a3 += (double)v * (double)f.w;
        }
        __syncthreads();
    }
    float4 r;
    r.x = (float)a0; r.y = (float)a1; r.z = (float)a2; r.w = (float)a3;
    __stcs(&out4[((size_t)seg << 8) + c], r);
}

// ---------------------------------------------------------------------------
extern "C" void kernel_launch(void* const* d_in, const int* in_sizes, int n_in,
                              void* d_out, int out_size) {
    const float* feats  = (const float*)d_in[0];
    const void*  idx    = d_in[1];
    const float* values = (const float*)d_in[2];
    float*       out    = (float*)d_out;

    init_kernel<<<(NSEG + 255) / 256, 256>>>((const int*)idx);
    count_kernel<<<(NNZ + 255) / 256, 256>>>(idx);
    scan_kernel<<<1, 1024>>>();
    scatter_kernel<<<(NNZ + 255) / 256, 256>>>(idx, values);
    gather_kernel<<<NSEG, 256>>>((const float4*)feats, (float4*)out);
}

// round 6
// speedup vs baseline: 4.6120x; 4.6120x over previous
#include <cuda_runtime.h>
#include <cuda_bf16.h>
#include <cstdint>

// Problem shapes (fixed by the dataset's setup_inputs)
#define B_DIM 8
#define S_DIM 4096
#define H_DIM 1024
#define G_DIM 1024
#define NNZ   (B_DIM * S_DIM)          // 32768
#define NSEG  (B_DIM * G_DIM)          // 8192
#define H4    (H_DIM / 4)              // 256 float4 per row
#define TPG   (S_DIM / G_DIM)          // 4 tokens per group
#if TPG != 4
#error "TPG assumed 4 (shift by 2)"
#endif

// Scratch (no device allocations allowed)
__device__ int   g_counts[NSEG];
__device__ int   g_offsets[NSEG + 1];
__device__ int   g_cursor[NSEG];
__device__ int   g_rows[NNZ];
__device__ float g_vals[NNZ];
__device__ int   g_is64;
__device__ int   g_nontrivial;

// ---------------------------------------------------------------------------
// 1) Fused init: zero counts + nontrivial flag (all blocks) and detect
//    indices dtype (block 0). Reads only the first 3*NNZ int32 (384 KB),
//    which is within the buffer for either dtype. Little-endian int64 with
//    small non-negative values => every odd int32 slot in that window is a
//    zero high-word; under int32 those slots hold real b/g data (nonzero).
// ---------------------------------------------------------------------------
__global__ void init_kernel(const int* __restrict__ p) {
    int i = blockIdx.x * blockDim.x + threadIdx.x;
    if (i < NSEG) g_counts[i] = 0;

    if (blockIdx.x == 0) {
        __shared__ int s_or[256];
        int tid = threadIdx.x;
        if (tid == 0) g_nontrivial = 0;
        int acc = 0;
        for (int k = 1 + 2 * tid; k < 3 * NNZ; k += 2 * 256)
            acc |= p[k];
        s_or[tid] = acc;
        __syncthreads();
        for (int off = 128; off > 0; off >>= 1) {
            if (tid < off) s_or[tid] |= s_or[tid + off];
            __syncthreads();
        }
        if (tid == 0) g_is64 = (s_or[0] == 0) ? 1 : 0;
    }
}

__device__ __forceinline__ void load_bgs(const void* idx, int i, int is64,
                                         int& b, int& g, int& s) {
    if (is64) {
        const long long* q = (const long long*)idx;
        b = (int)q[i];
        g = (int)q[NNZ + i];
        s = (int)q[2 * NNZ + i];
    } else {
        const int* q = (const int*)idx;
        b = q[i];
        g = q[NNZ + i];
        s = q[2 * NNZ + i];
    }
}

// ---------------------------------------------------------------------------
// 2) Count entries per segment + verify identity ordering for the fast path.
//    Entry i is "identity" iff (b,s,g) == (i/S, i%S, s/TPG). Only violating
//    entries issue the atomicOr.
// ---------------------------------------------------------------------------
__global__ void count_kernel(const void* __restrict__ idx) {
    int i = blockIdx.x * blockDim.x + threadIdx.x;
    if (i >= NNZ) return;
    int is64 = g_is64;
    int b, g, s;
    load_bgs(idx, i, is64, b, g, s);
    atomicAdd(&g_counts[b * G_DIM + g], 1);
    bool identity = (b == (i >> 12)) && (s == (i & (S_DIM - 1))) && (g == (s >> 2));
    if (!identity) atomicOr(&g_nontrivial, 1);
}

// ---------------------------------------------------------------------------
// 3) Exclusive scan over NSEG counts — single block, 1024 threads, shuffle
//    based, 2 barriers. Early-exits when the fast path will be taken
//    (offsets never read).
// ---------------------------------------------------------------------------
__global__ void __launch_bounds__(1024) scan_kernel() {
    if (g_nontrivial == 0) return;

    __shared__ int s_warp[32];
    int tid  = threadIdx.x;
    int lane = tid & 31;
    int wrp  = tid >> 5;

    int v[8];
    int tot = 0;
    int base = tid * 8;
#pragma unroll
    for (int k = 0; k < 8; ++k) { v[k] = g_counts[base + k]; tot += v[k]; }

    int inc = tot;
#pragma unroll
    for (int off = 1; off < 32; off <<= 1) {
        int t = __shfl_up_sync(0xFFFFFFFFu, inc, off);
        if (lane >= off) inc += t;
    }
    if (lane == 31) s_warp[wrp] = inc;
    __syncthreads();

    if (wrp == 0) {
        int w = s_warp[lane];
        int wi = w;
#pragma unroll
        for (int off = 1; off < 32; off <<= 1) {
            int t = __shfl_up_sync(0xFFFFFFFFu, wi, off);
            if (lane >= off) wi += t;
        }
        s_warp[lane] = wi - w;  // exclusive warp prefix
        if (lane == 31) g_offsets[NSEG] = wi;  // grand total
    }
    __syncthreads();

    int excl = s_warp[wrp] + (inc - tot);
#pragma unroll
    for (int k = 0; k < 8; ++k) {
        g_offsets[base + k] = excl;
        g_cursor[base + k]  = excl;
        excl += v[k];
    }
}

// ---------------------------------------------------------------------------
// 4) Scatter (row index into feats, value) into bucketed entry lists.
//    Early-exits on the fast path: saves a 768 KB idx reread + 32K atomics.
// ---------------------------------------------------------------------------
__global__ void scatter_kernel(const void* __restrict__ idx,
                               const float* __restrict__ values) {
    if (g_nontrivial == 0) return;
    int i = blockIdx.x * blockDim.x + threadIdx.x;
    if (i >= NNZ) return;
    int is64 = g_is64;
    int b, g, s;
    load_bgs(idx, i, is64, b, g, s);
    int seg = b * G_DIM + g;
    int pos = atomicAdd(&g_cursor[seg], 1);
    g_rows[pos] = b * S_DIM + s;
    g_vals[pos] = values[i];
}

// ---------------------------------------------------------------------------
// 5) Gather. Fast path (identity COO, runtime-verified): segment seg reads
//    feats rows 4*seg..4*seg+3 — a fully contiguous 16 KB region per block —
//    with 4 independent unrolled float4 loads per thread (MLP=4), no smem,
//    no barriers, deterministic fixed-order float accumulation.
//    Slow path: bucketed entries staged through shared memory.
//    feats touched exactly once -> __ldcs streaming; output -> __stcs.
// ---------------------------------------------------------------------------
__global__ void __launch_bounds__(256) gather_kernel(
    const float4* __restrict__ feats4,
    const float*  __restrict__ values,
    float4* __restrict__ out4) {
    int seg = blockIdx.x;
    int c   = threadIdx.x;          // 0..255 float4 chunks

    if (g_nontrivial == 0) {
        // ---- fast path ----
        size_t rowbase = ((size_t)seg << 2);   // 4*seg
        float v0 = __ldg(&values[4 * seg + 0]);
        float v1 = __ldg(&values[4 * seg + 1]);
        float v2 = __ldg(&values[4 * seg + 2]);
        float v3 = __ldg(&values[4 * seg + 3]);
        float4 f0 = __ldcs(&feats4[((rowbase + 0) << 8) + c]);
        float4 f1 = __ldcs(&feats4[((rowbase + 1) << 8) + c]);
        float4 f2 = __ldcs(&feats4[((rowbase + 2) << 8) + c]);
        float4 f3 = __ldcs(&feats4[((rowbase + 3) << 8) + c]);
        float4 r;
        r.x = fmaf(v3, f3.x, fmaf(v2, f2.x, fmaf(v1, f1.x, v0 * f0.x)));
        r.y = fmaf(v3, f3.y, fmaf(v2, f2.y, fmaf(v1, f1.y, v0 * f0.y)));
        r.z = fmaf(v3, f3.z, fmaf(v2, f2.z, fmaf(v1, f1.z, v0 * f0.z)));
        r.w = fmaf(v3, f3.w, fmaf(v2, f2.w, fmaf(v1, f1.w, v0 * f0.w)));
        __stcs(&out4[((size_t)seg << 8) + c], r);
        return;
    }

    // ---- general path ----
    __shared__ int   s_rows[64];
    __shared__ float s_vals[64];
    int start = __ldg(&g_offsets[seg]);
    int end   = __ldg(&g_offsets[seg + 1]);

    float a0 = 0.f, a1 = 0.f, a2 = 0.f, a3 = 0.f;
    for (int base = start; base < end; base += 64) {
        int n = min(64, end - base);
        if (c < n) {
            s_rows[c] = g_rows[base + c];
            s_vals[c] = g_vals[base + c];
        }
        __syncthreads();
        for (int j = 0; j < n; ++j) {
            int   row = s_rows[j];
            float v   = s_vals[j];
            float4 f  = __ldcs(&feats4[((size_t)row << 8) + c]);
            a0 = fmaf(v, f.x, a0);
            a1 = fmaf(v, f.y, a1);
            a2 = fmaf(v, f.z, a2);
            a3 = fmaf(v, f.w, a3);
        }
        __syncthreads();
    }
    float4 r;
    r.x = a0; r.y = a1; r.z = a2; r.w = a3;
    __stcs(&out4[((size_t)seg << 8) + c], r);
}

// ---------------------------------------------------------------------------
extern "C" void kernel_launch(void* const* d_in, const int* in_sizes, int n_in,
                              void* d_out, int out_size) {
    const float* feats  = (const float*)d_in[0];
    const void*  idx    = d_in[1];
    const float* values = (const float*)d_in[2];
    float*       out    = (float*)d_out;

    init_kernel<<<(NSEG + 255) / 256, 256>>>((const int*)idx);
    count_kernel<<<(NNZ + 127) / 128, 128>>>(idx);
    scan_kernel<<<1, 1024>>>();
    scatter_kernel<<<(NNZ + 127) / 128, 128>>>(idx, values);
    gather_kernel<<<NSEG, 256>>>((const float4*)feats, values, (float4*)out);
}